// round 9
// baseline (speedup 1.0000x reference)
#include <cuda_runtime.h>
#include <cuda_fp16.h>
#include <float.h>
#include <cstdint>

#define B_   8
#define C_   64
#define N_   4096
#define K_   20
#define M_   8
#define OUTC 64
#define CM   512          // C_*M_
#define PTS  (B_*N_)      // 32768

// Scratch (allocation-free rule: __device__ globals)
__device__ __align__(16) __half g_ftH[B_*N_*C_];   // feature fp16 [b][n][c] (4 MB)
__device__ __align__(16) __half g_wh[CM*OUTC];     // conv_w fp16 [oc][j]   (64 KB)

__device__ __forceinline__ uint32_t smem_u32(const void* p) {
    uint32_t a;
    asm("{ .reg .u64 t; cvta.to.shared.u64 t, %1; cvt.u32.u64 %0, t; }" : "=r"(a) : "l"(p));
    return a;
}
__device__ __forceinline__ void ffma2(unsigned long long& d,
                                      unsigned long long a, unsigned long long b) {
    asm("fma.rn.f32x2 %0, %1, %2, %0;" : "+l"(d) : "l"(a), "l"(b));
}
__device__ __forceinline__ unsigned long long pack2(float x, float y) {
    unsigned long long r;
    asm("mov.b64 %0, {%1, %2};" : "=l"(r) : "f"(x), "f"(y));
    return r;
}
__device__ __forceinline__ float2 unpack2(unsigned long long v) {
    float2 f;
    asm("mov.b64 {%0, %1}, %2;" : "=f"(f.x), "=f"(f.y) : "l"(v));
    return f;
}

// ===========================================================================
// K1: feature (B,C,N) fp32 -> g_ftH (B,N,C) fp16
// ===========================================================================
__global__ void k_transpose_feat(const float* __restrict__ feat) {
    __shared__ float tile[32][33];
    const int b  = blockIdx.z;
    const int c0 = blockIdx.y * 32;
    const int n0 = blockIdx.x * 32;
    const int tx = threadIdx.x, ty = threadIdx.y;   // block (32,8)
    const float* fb = feat + (size_t)b * C_ * N_;
    #pragma unroll
    for (int r = 0; r < 4; r++)
        tile[ty + 8*r][tx] = fb[(size_t)(c0 + ty + 8*r) * N_ + (n0 + tx)];
    __syncthreads();
    __half* ob = g_ftH + (size_t)b * N_ * C_;
    #pragma unroll
    for (int r = 0; r < 4; r++)
        ob[(size_t)(n0 + ty + 8*r) * C_ + (c0 + tx)] = __float2half(tile[tx][ty + 8*r]);
}

// ===========================================================================
// K2: conv_w fp32 [oc][j] -> fp16 g_wh (same layout)
// ===========================================================================
__global__ void k_prep_w(const float* __restrict__ w) {
    int i = blockIdx.x * blockDim.x + threadIdx.x;
    if (i < CM * OUTC) g_wh[i] = __float2half(w[i]);
}

// ===========================================================================
// Fused kernel: per CTA, 64 points.
//   Phase A: softmax + gather-aggregation -> smem A tile (fp16, 64 x 512)
//   Phase B: HMMA GEMM vs W (cp.async double-buffered 64-k chunks)
//   Epilogue: bias + leaky_relu + residual
// ===========================================================================
#define AS 520            // halves per A row (512 + 8 pad; 1040 B, %128 = 16)
#define BS 72             // halves per W-chunk row (64 + 8)
#define OS 68             // floats per out-stage row

// smem offsets (bytes)
#define OFF_A    0                        // 64*520*2        = 66560
#define OFF_W    66560                    // 2*64*72*2       = 18432
#define OFF_PS   (66560 + 18432)          // 8*20*8*4        =  5120
#define OFF_IDX  (OFF_PS + 5120)          // 8*20*4          =   640
#define SMEM_FUSED (OFF_IDX + 640)        // 90752 B
// epilogue stage overlays OFF_A (64*68*4 = 17408 B)

__global__ void __launch_bounds__(256) k_fused(
    const float* __restrict__ x,
    const int*   __restrict__ nidx,
    const float* __restrict__ kern,
    const float* __restrict__ bias,
    const float* __restrict__ feat,
    float*       __restrict__ out)
{
    extern __shared__ char smem[];
    __half* Atile = (__half*)(smem + OFF_A);
    __half* Wst   = (__half*)(smem + OFF_W);       // 2 stages of 64*BS
    float (*ps)[20][8] = (float (*)[20][8])(smem + OFF_PS);
    int   (*idxs)[20]  = (int (*)[20])(smem + OFF_IDX);

    const int tid  = threadIdx.x;
    const int wid  = tid >> 5;
    const int lane = tid & 31;
    const int ptBase = blockIdx.x * 64;
    const int b    = ptBase >> 12;                 // whole tile in one batch

    // ---- kick W chunk 0 (background during phase A) ----
    {
        #pragma unroll
        for (int i = 0; i < 2; i++) {
            const int c   = tid + i * 256;
            const int row = c >> 3;
            const int c8  = c & 7;
            asm volatile("cp.async.cg.shared.global [%0], [%1], 16;" ::
                "r"(smem_u32(Wst + row * BS + c8 * 8)),
                "l"(g_wh + (size_t)row * CM + c8 * 8));
        }
        asm volatile("cp.async.commit_group;");
    }

    // =======================================================================
    // Phase A: each warp computes 8 points (rows wid*8 .. wid*8+7)
    // =======================================================================
    const float* xb  = x + (size_t)b * 3 * N_;
    const __half* ftb = g_ftH + (size_t)b * N_ * C_;

    for (int p = 0; p < 8; p++) {
        const int row = wid * 8 + p;
        const int pt  = ptBase + row;

        float px[8];
        float x0 = 0.f, x1 = 0.f, x2 = 0.f;
        if (lane < K_) {
            int ik = nidx[pt * K_ + lane] & (N_ - 1);
            idxs[wid][lane] = ik;
            x0 = xb[ik];
            x1 = xb[N_ + ik];
            x2 = xb[2*N_ + ik];
        }
        const float r0 = x0 - __shfl_sync(0xFFFFFFFFu, x0, 0);
        const float r1 = x1 - __shfl_sync(0xFFFFFFFFu, x1, 0);
        const float r2 = x2 - __shfl_sync(0xFFFFFFFFu, x2, 0);

        #pragma unroll
        for (int m = 0; m < M_; m++) {
            float v = r0 * kern[m] + r1 * kern[M_ + m] + r2 * kern[2*M_ + m];
            if (lane == 0 && m == 0) v += 1.0f;   // one_pad
            px[m] = (lane < K_) ? v : -FLT_MAX;
        }

        #pragma unroll
        for (int m = 0; m < M_; m++) {
            float mx = px[m];
            #pragma unroll
            for (int o = 16; o > 0; o >>= 1)
                mx = fmaxf(mx, __shfl_xor_sync(0xFFFFFFFFu, mx, o));
            float e = (lane < K_) ? __expf(px[m] - mx) : 0.f;
            float s = e;
            #pragma unroll
            for (int o = 16; o > 0; o >>= 1)
                s += __shfl_xor_sync(0xFFFFFFFFu, s, o);
            px[m] = e * (1.0f / s);
        }
        if (lane < K_) {
            float4* dst = (float4*)ps[wid][lane];
            dst[0] = make_float4(px[0], px[1], px[2], px[3]);
            dst[1] = make_float4(px[4], px[5], px[6], px[7]);
        }
        __syncwarp();

        // aggregation: lane owns channels 2*lane, 2*lane+1
        const int c0 = lane * 2;
        unsigned long long accA[4] = {0,0,0,0};
        unsigned long long accB[4] = {0,0,0,0};
        union f4u { float4 v; unsigned long long u[2]; };

        #pragma unroll
        for (int k = 0; k < K_; k++) {
            const int ii = idxs[wid][k];
            const float2 f = __half22float2(*(const __half2*)(ftb + (size_t)ii * C_ + c0));
            const unsigned long long fxx = pack2(f.x, f.x);
            const unsigned long long fyy = pack2(f.y, f.y);
            f4u pa, pb;
            pa.v = *((const float4*)ps[wid][k]);
            pb.v = *((const float4*)ps[wid][k] + 1);
            ffma2(accA[0], fxx, pa.u[0]);  ffma2(accA[1], fxx, pa.u[1]);
            ffma2(accA[2], fxx, pb.u[0]);  ffma2(accA[3], fxx, pb.u[1]);
            ffma2(accB[0], fyy, pa.u[0]);  ffma2(accB[1], fyy, pa.u[1]);
            ffma2(accB[2], fyy, pb.u[0]);  ffma2(accB[3], fyy, pb.u[1]);
        }

        // fp16 pack straight into the smem A tile (j = 16*lane .. +15)
        __half2 h[8];
        #pragma unroll
        for (int i = 0; i < 4; i++) {
            const float2 fa = unpack2(accA[i]);
            const float2 fb = unpack2(accB[i]);
            h[i]     = __floats2half2_rn(fa.x, fa.y);
            h[4 + i] = __floats2half2_rn(fb.x, fb.y);
        }
        __half* dst = Atile + (size_t)row * AS + 16 * lane;
        *(uint4*)(dst)     = *(uint4*)(h);
        *(uint4*)(dst + 8) = *(uint4*)(h + 4);
        __syncwarp();
    }
    __syncthreads();

    // =======================================================================
    // Phase B: HMMA GEMM: out[64pt][64oc] = A(64x512) @ W^T
    // =======================================================================
    const int warp_m = (wid & 3) * 16;   // 4 warps over 64 pts
    const int warp_n = (wid >> 2) * 32;  // 2 warps over 64 ocs

    float acc[4][4];
    #pragma unroll
    for (int ni = 0; ni < 4; ni++)
        #pragma unroll
        for (int r = 0; r < 4; r++) acc[ni][r] = 0.f;

    for (int kc8 = 0; kc8 < 8; kc8++) {
        if (kc8 < 7) {
            const int kc = (kc8 + 1) * 64;
            __half* wdst = Wst + ((kc8 + 1) & 1) * 64 * BS;
            #pragma unroll
            for (int i = 0; i < 2; i++) {
                const int c   = tid + i * 256;
                const int row = c >> 3;
                const int c8  = c & 7;
                asm volatile("cp.async.cg.shared.global [%0], [%1], 16;" ::
                    "r"(smem_u32(wdst + row * BS + c8 * 8)),
                    "l"(g_wh + (size_t)row * CM + kc + c8 * 8));
            }
            asm volatile("cp.async.commit_group;");
            asm volatile("cp.async.wait_group 1;");
        } else {
            asm volatile("cp.async.wait_group 0;");
        }
        __syncthreads();

        const __half* wst = Wst + (kc8 & 1) * 64 * BS;
        #pragma unroll
        for (int ks = 0; ks < 4; ks++) {
            const int ksg = kc8 * 4 + ks;
            uint32_t a[4];
            {
                const uint32_t addr = smem_u32(
                    Atile + (size_t)(warp_m + (lane & 15)) * AS
                          + ksg * 16 + (lane >> 4) * 8);
                asm volatile("ldmatrix.sync.aligned.m8n8.x4.shared.b16 "
                             "{%0,%1,%2,%3}, [%4];"
                             : "=r"(a[0]), "=r"(a[1]), "=r"(a[2]), "=r"(a[3])
                             : "r"(addr));
            }
            uint32_t bfr[4][2];
            #pragma unroll
            for (int ni = 0; ni < 4; ni++) {
                const uint32_t addr = smem_u32(
                    wst + (warp_n + ni * 8 + (lane & 7)) * BS
                        + ks * 16 + ((lane >> 3) & 1) * 8);
                asm volatile("ldmatrix.sync.aligned.m8n8.x2.shared.b16 "
                             "{%0,%1}, [%2];"
                             : "=r"(bfr[ni][0]), "=r"(bfr[ni][1])
                             : "r"(addr));
            }
            #pragma unroll
            for (int ni = 0; ni < 4; ni++) {
                asm volatile(
                    "mma.sync.aligned.m16n8k16.row.col.f32.f16.f16.f32 "
                    "{%0,%1,%2,%3}, {%4,%5,%6,%7}, {%8,%9}, {%0,%1,%2,%3};"
                    : "+f"(acc[ni][0]), "+f"(acc[ni][1]),
                      "+f"(acc[ni][2]), "+f"(acc[ni][3])
                    : "r"(a[0]), "r"(a[1]), "r"(a[2]), "r"(a[3]),
                      "r"(bfr[ni][0]), "r"(bfr[ni][1]));
            }
        }
        __syncthreads();
    }

    // ---- scatter fragments to smem [oc][pt] (overlays dead A tile) ----
    float* osm = (float*)(smem + OFF_A);
    {
        const int r  = lane >> 2;
        const int cp = (lane & 3) * 2;
        #pragma unroll
        for (int ni = 0; ni < 4; ni++) {
            const int pt0 = warp_m + r;
            const int oc0 = warp_n + ni * 8 + cp;
            osm[oc0 * OS + pt0]           = acc[ni][0];
            osm[(oc0 + 1) * OS + pt0]     = acc[ni][1];
            osm[oc0 * OS + pt0 + 8]       = acc[ni][2];
            osm[(oc0 + 1) * OS + pt0 + 8] = acc[ni][3];
        }
    }
    __syncthreads();

    // ---- fused epilogue: bias + leaky_relu + residual ----
    const int n0 = ptBase & (N_ - 1);
    #pragma unroll
    for (int i = 0; i < 4; i++) {
        const int c    = tid + i * 256;    // 1024 float4 tasks
        const int oc   = c >> 4;
        const int col4 = (c & 15) * 4;
        const float* src = osm + oc * OS + col4;
        const size_t o = ((size_t)(b * OUTC + oc)) * N_ + n0 + col4;
        const float4 f = *(const float4*)(feat + o);
        const float bb = bias[oc];
        float4 v;
        v.x = src[0] + bb; v.x = (v.x > 0.f ? v.x : 0.2f * v.x) + f.x;
        v.y = src[1] + bb; v.y = (v.y > 0.f ? v.y : 0.2f * v.y) + f.y;
        v.z = src[2] + bb; v.z = (v.z > 0.f ? v.z : 0.2f * v.z) + f.z;
        v.w = src[3] + bb; v.w = (v.w > 0.f ? v.w : 0.2f * v.w) + f.w;
        *(float4*)(out + o) = v;
    }
}

// ===========================================================================
extern "C" void kernel_launch(void* const* d_in, const int* in_sizes, int n_in,
                              void* d_out, int out_size) {
    const float* x    = (const float*)d_in[0];
    const float* feat = (const float*)d_in[1];
    const int*   nidx = (const int*)d_in[2];     // int32: JAX x64 is disabled
    const float* kern = (const float*)d_in[3];
    const float* w    = (const float*)d_in[4];
    const float* bias = (const float*)d_in[5];
    float* out = (float*)d_out;

    cudaFuncSetAttribute(k_fused, cudaFuncAttributeMaxDynamicSharedMemorySize, SMEM_FUSED);

    k_transpose_feat<<<dim3(N_/32, C_/32, B_), dim3(32, 8)>>>(feat);
    k_prep_w<<<(CM*OUTC + 255)/256, 256>>>(w);
    k_fused<<<PTS/64, 256, SMEM_FUSED>>>(x, nidx, kern, bias, feat, out);
}

// round 10
// speedup vs baseline: 1.4412x; 1.4412x over previous
#include <cuda_runtime.h>
#include <cuda_fp16.h>
#include <float.h>
#include <cstdint>

#define B_   8
#define C_   64
#define N_   4096
#define K_   20
#define M_   8
#define OUTC 64
#define CM   512          // C_*M_
#define PTS  (B_*N_)      // 32768

// Scratch (allocation-free rule: __device__ globals)
__device__ __align__(16) __half g_ftH[B_*N_*C_];           // feature fp16 [b][n][c] (4 MB)
__device__ __align__(16) __half g_aggH[(size_t)PTS*CM];    // agg fp16 [pt][j]      (32 MB)
__device__ __align__(16) __half g_wh[CM*OUTC];             // conv_w fp16 [oc][j]   (64 KB)
__device__ __align__(16) float4 g_x4[PTS];                 // packed coords         (512 KB)

__device__ __forceinline__ uint32_t smem_u32(const void* p) {
    uint32_t a;
    asm("{ .reg .u64 t; cvta.to.shared.u64 t, %1; cvt.u32.u64 %0, t; }" : "=r"(a) : "l"(p));
    return a;
}
__device__ __forceinline__ void ffma2(unsigned long long& d,
                                      unsigned long long a, unsigned long long b) {
    asm("fma.rn.f32x2 %0, %1, %2, %0;" : "+l"(d) : "l"(a), "l"(b));
}
__device__ __forceinline__ unsigned long long pack2(float x, float y) {
    unsigned long long r;
    asm("mov.b64 %0, {%1, %2};" : "=l"(r) : "f"(x), "f"(y));
    return r;
}
__device__ __forceinline__ float2 unpack2(unsigned long long v) {
    float2 f;
    asm("mov.b64 {%0, %1}, %2;" : "=f"(f.x), "=f"(f.y) : "l"(v));
    return f;
}

// ===========================================================================
// K1: feature (B,C,N) fp32 -> g_ftH (B,N,C) fp16; both sides 128B-coalesced
// ===========================================================================
__global__ void k_transpose_feat(const float* __restrict__ feat) {
    __shared__ float tile[32][66];                 // [n][c], +2 pad
    const int b  = blockIdx.z;
    const int n0 = blockIdx.x * 32;
    const int tx = threadIdx.x, ty = threadIdx.y;  // block (32,8)
    const float* fb = feat + (size_t)b * C_ * N_;
    #pragma unroll
    for (int cc = 0; cc < 8; cc++) {
        const int c = cc * 8 + ty;
        tile[tx][c] = fb[(size_t)c * N_ + n0 + tx];   // 128B coalesced per warp
    }
    __syncthreads();
    __half* ob = g_ftH + (size_t)b * N_ * C_;
    #pragma unroll
    for (int r = 0; r < 4; r++) {
        const int n = r * 8 + ty;
        const float2 v = *(const float2*)&tile[n][2 * tx];
        *(__half2*)(ob + (size_t)(n0 + n) * C_ + 2 * tx) =
            __floats2half2_rn(v.x, v.y);              // 128B coalesced per warp
    }
}

// ===========================================================================
// Prep: conv_w -> fp16, and x -> packed float4 per point (both 32768 items)
// ===========================================================================
__global__ void k_prep(const float* __restrict__ w, const float* __restrict__ x) {
    const int i = blockIdx.x * blockDim.x + threadIdx.x;   // 0 .. 32767
    g_wh[i] = __float2half(w[i]);
    const int b = i >> 12;
    const int n = i & (N_ - 1);
    const float* xb = x + (size_t)b * 3 * N_;
    g_x4[i] = make_float4(xb[n], xb[N_ + n], xb[2*N_ + n], 0.f);
}

// ===========================================================================
// K3: warp-per-point: perm matrix + softmax + aggregation -> g_aggH[pt][j]
//     packed-x gather, batched feature gathers, no-max softmax
// ===========================================================================
__global__ void __launch_bounds__(256) k_agg(
    const int*   __restrict__ nidx,          // int32 (JAX x64 disabled)
    const float* __restrict__ kern)
{
    const int warp = threadIdx.x >> 5;
    const int lane = threadIdx.x & 31;
    const int pt   = blockIdx.x * 8 + warp;
    const int b    = pt >> 12;

    __shared__ int   idx_s[8][20];
    __shared__ float p_s[8][20][8];

    float px[8];
    float x0 = 0.f, x1 = 0.f, x2 = 0.f;
    if (lane < K_) {
        const int ik = nidx[pt * K_ + lane] & (N_ - 1);
        idx_s[warp][lane] = ik;
        const float4 xv = g_x4[(b << 12) + ik];
        x0 = xv.x; x1 = xv.y; x2 = xv.z;
    }
    const float r0 = x0 - __shfl_sync(0xFFFFFFFFu, x0, 0);
    const float r1 = x1 - __shfl_sync(0xFFFFFFFFu, x1, 0);
    const float r2 = x2 - __shfl_sync(0xFFFFFFFFu, x2, 0);

    #pragma unroll
    for (int m = 0; m < M_; m++) {
        float v = r0 * kern[m] + r1 * kern[M_ + m] + r2 * kern[2*M_ + m];
        if (lane == 0 && m == 0) v += 1.0f;       // one_pad
        px[m] = v;
    }

    // softmax over k (no max-shift: |logit| <~ 20, exp safe in fp32)
    #pragma unroll
    for (int m = 0; m < M_; m++) {
        const float e = (lane < K_) ? __expf(px[m]) : 0.f;
        float s = e;
        #pragma unroll
        for (int o = 16; o > 0; o >>= 1)
            s += __shfl_xor_sync(0xFFFFFFFFu, s, o);
        px[m] = e * (1.0f / s);
    }
    if (lane < K_) {
        float4* dst = (float4*)p_s[warp][lane];
        dst[0] = make_float4(px[0], px[1], px[2], px[3]);
        dst[1] = make_float4(px[4], px[5], px[6], px[7]);
    }
    __syncwarp();

    // ---- batched feature gather: 20 coalesced half2 loads up front ----
    const int c0 = lane * 2;
    const __half* ftb = g_ftH + ((size_t)b << 12) * C_;
    uint32_t f[20];
    #pragma unroll
    for (int k = 0; k < K_; k++)
        f[k] = *(const uint32_t*)(ftb + (size_t)idx_s[warp][k] * C_ + c0);

    unsigned long long accA[4] = {0,0,0,0};   // channel c0
    unsigned long long accB[4] = {0,0,0,0};   // channel c0+1
    union f4u { float4 v; unsigned long long u[2]; };

    #pragma unroll
    for (int k = 0; k < K_; k++) {
        const float2 fc = __half22float2(*(__half2*)&f[k]);
        const unsigned long long fxx = pack2(fc.x, fc.x);
        const unsigned long long fyy = pack2(fc.y, fc.y);
        f4u pa, pb;
        pa.v = *((const float4*)p_s[warp][k]);
        pb.v = *((const float4*)p_s[warp][k] + 1);
        ffma2(accA[0], fxx, pa.u[0]);  ffma2(accA[1], fxx, pa.u[1]);
        ffma2(accA[2], fxx, pb.u[0]);  ffma2(accA[3], fxx, pb.u[1]);
        ffma2(accB[0], fyy, pa.u[0]);  ffma2(accB[1], fyy, pa.u[1]);
        ffma2(accB[2], fyy, pb.u[0]);  ffma2(accB[3], fyy, pb.u[1]);
    }

    // fp16 pack: lane's 16 values are j = 16*lane .. 16*lane+15
    __half2 h[8];
    #pragma unroll
    for (int i = 0; i < 4; i++) {
        const float2 fa = unpack2(accA[i]);
        const float2 fb = unpack2(accB[i]);
        h[i]     = __floats2half2_rn(fa.x, fa.y);
        h[4 + i] = __floats2half2_rn(fb.x, fb.y);
    }
    __half* dst = g_aggH + (size_t)pt * CM + 16 * lane;
    *(uint4*)(dst)     = *(uint4*)(h);
    *(uint4*)(dst + 8) = *(uint4*)(h + 4);
}

// ===========================================================================
// K4: HMMA fp16 GEMM, 64pt x 64oc tiles (grid 512), cp.async double buffer
// ===========================================================================
#define AS_STRIDE 72
#define BS_STRIDE 72
#define OS_STRIDE 68

struct Stage { __half a[64 * AS_STRIDE]; __half b[64 * BS_STRIDE]; };

__global__ void __launch_bounds__(256) k_gemm_hmma(
    const float* __restrict__ bias,
    const float* __restrict__ feat,
    float* __restrict__ out)
{
    __shared__ union {
        Stage st[2];
        float o[64 * OS_STRIDE];
    } sm;

    const int tid  = threadIdx.x;
    const int wid  = tid >> 5;
    const int lane = tid & 31;
    const int warp_m = (wid & 3) * 16;   // 4 warps over 64 pts
    const int warp_n = (wid >> 2) * 32;  // 2 warps over 64 ocs
    const int ptBase = blockIdx.x * 64;

    float acc[4][4];
    #pragma unroll
    for (int ni = 0; ni < 4; ni++)
        #pragma unroll
        for (int r = 0; r < 4; r++) acc[ni][r] = 0.f;

    const __half* aSrc = g_aggH + (size_t)ptBase * CM;

    auto load_chunk = [&](int s, int kc) {
        #pragma unroll
        for (int i = 0; i < 2; i++) {
            const int c   = tid + i * 256;
            const int row = c >> 3;
            const int c8  = c & 7;
            asm volatile("cp.async.cg.shared.global [%0], [%1], 16;" ::
                "r"(smem_u32(sm.st[s].a + row * AS_STRIDE + c8 * 8)),
                "l"(aSrc + (size_t)row * CM + kc + c8 * 8));
        }
        #pragma unroll
        for (int i = 0; i < 2; i++) {
            const int c   = tid + i * 256;
            const int row = c >> 3;
            const int c8  = c & 7;
            asm volatile("cp.async.cg.shared.global [%0], [%1], 16;" ::
                "r"(smem_u32(sm.st[s].b + row * BS_STRIDE + c8 * 8)),
                "l"(g_wh + (size_t)row * CM + kc + c8 * 8));
        }
    };

    load_chunk(0, 0);
    asm volatile("cp.async.commit_group;");

    for (int kc8 = 0; kc8 < 8; kc8++) {
        if (kc8 < 7) {
            load_chunk((kc8 + 1) & 1, (kc8 + 1) * 64);
            asm volatile("cp.async.commit_group;");
            asm volatile("cp.async.wait_group 1;");
        } else {
            asm volatile("cp.async.wait_group 0;");
        }
        __syncthreads();

        const Stage& st = sm.st[kc8 & 1];
        #pragma unroll
        for (int ks = 0; ks < 4; ks++) {
            uint32_t a[4];
            {
                const uint32_t addr = smem_u32(
                    st.a + (warp_m + (lane & 15)) * AS_STRIDE
                         + ks * 16 + (lane >> 4) * 8);
                asm volatile("ldmatrix.sync.aligned.m8n8.x4.shared.b16 "
                             "{%0,%1,%2,%3}, [%4];"
                             : "=r"(a[0]), "=r"(a[1]), "=r"(a[2]), "=r"(a[3])
                             : "r"(addr));
            }
            uint32_t bfr[4][2];
            #pragma unroll
            for (int ni = 0; ni < 4; ni++) {
                const uint32_t addr = smem_u32(
                    st.b + (warp_n + ni * 8 + (lane & 7)) * BS_STRIDE
                         + ks * 16 + ((lane >> 3) & 1) * 8);
                asm volatile("ldmatrix.sync.aligned.m8n8.x2.shared.b16 "
                             "{%0,%1}, [%2];"
                             : "=r"(bfr[ni][0]), "=r"(bfr[ni][1])
                             : "r"(addr));
            }
            #pragma unroll
            for (int ni = 0; ni < 4; ni++) {
                asm volatile(
                    "mma.sync.aligned.m16n8k16.row.col.f32.f16.f16.f32 "
                    "{%0,%1,%2,%3}, {%4,%5,%6,%7}, {%8,%9}, {%0,%1,%2,%3};"
                    : "+f"(acc[ni][0]), "+f"(acc[ni][1]),
                      "+f"(acc[ni][2]), "+f"(acc[ni][3])
                    : "r"(a[0]), "r"(a[1]), "r"(a[2]), "r"(a[3]),
                      "r"(bfr[ni][0]), "r"(bfr[ni][1]));
            }
        }
        __syncthreads();
    }

    // scatter fragments to smem as [oc][pt]
    {
        const int r  = lane >> 2;
        const int cp = (lane & 3) * 2;
        #pragma unroll
        for (int ni = 0; ni < 4; ni++) {
            const int pt0 = warp_m + r;
            const int oc0 = warp_n + ni * 8 + cp;
            sm.o[oc0 * OS_STRIDE + pt0]           = acc[ni][0];
            sm.o[(oc0 + 1) * OS_STRIDE + pt0]     = acc[ni][1];
            sm.o[oc0 * OS_STRIDE + pt0 + 8]       = acc[ni][2];
            sm.o[(oc0 + 1) * OS_STRIDE + pt0 + 8] = acc[ni][3];
        }
    }
    __syncthreads();

    // fused epilogue: bias + leaky_relu + residual, coalesced float4 stores
    const int b  = ptBase >> 12;
    const int n0 = ptBase & (N_ - 1);
    #pragma unroll
    for (int i = 0; i < 4; i++) {
        const int c    = tid + i * 256;    // 1024 float4 tasks
        const int oc   = c >> 4;
        const int col4 = (c & 15) * 4;
        const float* src = sm.o + oc * OS_STRIDE + col4;
        const size_t o = ((size_t)(b * OUTC + oc)) * N_ + n0 + col4;
        const float4 f = *(const float4*)(feat + o);
        const float bb = bias[oc];
        float4 v;
        v.x = src[0] + bb; v.x = (v.x > 0.f ? v.x : 0.2f * v.x) + f.x;
        v.y = src[1] + bb; v.y = (v.y > 0.f ? v.y : 0.2f * v.y) + f.y;
        v.z = src[2] + bb; v.z = (v.z > 0.f ? v.z : 0.2f * v.z) + f.z;
        v.w = src[3] + bb; v.w = (v.w > 0.f ? v.w : 0.2f * v.w) + f.w;
        *(float4*)(out + o) = v;
    }
}

// ===========================================================================
extern "C" void kernel_launch(void* const* d_in, const int* in_sizes, int n_in,
                              void* d_out, int out_size) {
    const float* x    = (const float*)d_in[0];
    const float* feat = (const float*)d_in[1];
    const int*   nidx = (const int*)d_in[2];     // int32: JAX x64 is disabled
    const float* kern = (const float*)d_in[3];
    const float* w    = (const float*)d_in[4];
    const float* bias = (const float*)d_in[5];
    float* out = (float*)d_out;

    k_transpose_feat<<<dim3(N_/32, 1, B_), dim3(32, 8)>>>(feat);
    k_prep<<<PTS/256, 256>>>(w, x);
    k_agg<<<PTS/8, 256>>>(nidx, kern);
    k_gemm_hmma<<<PTS/64, 256>>>(bias, feat, out);
}